// round 15
// baseline (speedup 1.0000x reference)
#include <cuda_runtime.h>
#include <cuda_fp16.h>
#include <cstdint>
#include <cstddef>

// ---------------------------------------------------------------------------
// Problem constants
// ---------------------------------------------------------------------------
#define B_SZ   8192
#define D_SZ   8
#define P_SZ   10
#define R_SZ   512
#define OUT_SZ 64
#define NMID   6
#define KTOT   (P_SZ * R_SZ)       // 5120
#define KC     32                  // K per SUB-chunk
#define NCH2   (KTOT / (2 * KC))   // 80 big chunks (64 k each)

// ---------------------------------------------------------------------------
// Device-global scratch
// ---------------------------------------------------------------------------
__device__ float  g_tanh_g0[P_SZ * R_SZ];
__device__ __half g_qa[(size_t)B_SZ * R_SZ];      // fp16 of res/s (per-row scaled)
__device__ float  g_sa[B_SZ];                     // per-row scale
// B operands: tanh'd, transposed to [n][k=j*512+r], single fp16 (|tanh|<=0.1)
__device__ __half g_b_mid[(size_t)NMID * R_SZ * KTOT];
__device__ __half g_b_last[(size_t)OUT_SZ * KTOT];

// ---------------------------------------------------------------------------
// PTX helpers (sm_80-era: cp.async, ldmatrix, mma.sync — NO tcgen05)
// ---------------------------------------------------------------------------
__device__ __forceinline__ uint32_t smem_u32(const void* p) {
    uint32_t a;
    asm("{ .reg .u64 t; cvta.to.shared.u64 t, %1; cvt.u32.u64 %0, t; }" : "=r"(a) : "l"(p));
    return a;
}
#define CP_ASYNC16(dst, src) \
    asm volatile("cp.async.cg.shared.global [%0], [%1], 16;" :: "r"(dst), "l"(src) : "memory")
#define CP_COMMIT() asm volatile("cp.async.commit_group;" ::: "memory")
#define CP_WAIT1()  asm volatile("cp.async.wait_group 1;" ::: "memory")
#define CP_WAIT2()  asm volatile("cp.async.wait_group 2;" ::: "memory")

#define LDSM4(r0, r1, r2, r3, addr) \
    asm volatile("ldmatrix.sync.aligned.m8n8.x4.shared.b16 {%0,%1,%2,%3}, [%4];" \
                 : "=r"(r0), "=r"(r1), "=r"(r2), "=r"(r3) : "r"(addr))

#define MMA_F16(d, a, b) \
    asm volatile("mma.sync.aligned.m16n8k16.row.col.f32.f16.f16.f32 " \
                 "{%0,%1,%2,%3}, {%4,%5,%6,%7}, {%8,%9}, {%0,%1,%2,%3};" \
                 : "+f"((d)[0]), "+f"((d)[1]), "+f"((d)[2]), "+f"((d)[3]) \
                 : "r"((a)[0]), "r"((a)[1]), "r"((a)[2]), "r"((a)[3]), \
                   "r"((b)[0]), "r"((b)[1]))

// 64B-row XOR swizzle: conflict-free across all 8-row ldmatrix phases.
__device__ __forceinline__ uint32_t sw64(uint32_t row, uint32_t c16) {
    return row * 64u + ((c16 ^ ((row >> 1) & 3u)) << 4);
}

// ---------------------------------------------------------------------------
// Precompute: tanh + transpose -> single fp16
//   G [R, P, N] (n contiguous) -> B [n][j*512 + r] (k contiguous)
// ---------------------------------------------------------------------------
__global__ void trans_f16_kernel(const float* __restrict__ G,
                                 __half* __restrict__ bo,
                                 int N, size_t gStride, size_t oStride) {
    __shared__ float t[32][33];
    int layer = blockIdx.z / P_SZ;
    int j     = blockIdx.z % P_SZ;
    const float* Gp = G + (size_t)layer * gStride;
    __half* bop = bo + (size_t)layer * oStride;
    int rt = blockIdx.x * 32, nt = blockIdx.y * 32;
    int tx = threadIdx.x, ty = threadIdx.y;   // block (32, 8)
#pragma unroll
    for (int yy = ty; yy < 32; yy += 8)
        t[yy][tx] = tanhf(Gp[((size_t)(rt + yy) * P_SZ + j) * N + nt + tx]);
    __syncthreads();
#pragma unroll
    for (int yy = ty; yy < 32; yy += 8) {
        int n = nt + yy, r = rt + tx;
        bop[(size_t)n * KTOT + (size_t)j * R_SZ + r] = __float2half_rn(t[tx][yy]);
    }
}

__global__ void tanh_small_kernel(const float* __restrict__ src,
                                  float* __restrict__ dst, int n) {
    int i = blockIdx.x * blockDim.x + threadIdx.x;
    if (i < n) dst[i] = tanhf(src[i]);
}

// First core + fused quantization: res0[b,r] -> qa, sa directly.
__global__ void first_core_quant_kernel(const float* __restrict__ z,
                                        __half* __restrict__ qa,
                                        float* __restrict__ sa) {
    __shared__ float wmax[16];
    int b = blockIdx.x;
    int r = threadIdx.x;     // 512 threads
    float zv = z[b * D_SZ + 0];
    float ph = 1.f, acc = 0.f;
#pragma unroll
    for (int j = 0; j < P_SZ; j++) {
        acc += g_tanh_g0[j * R_SZ + r] * ph;
        ph *= zv;
    }
    float a = fabsf(acc);
#pragma unroll
    for (int o = 16; o; o >>= 1) a = fmaxf(a, __shfl_xor_sync(0xffffffffu, a, o));
    if ((r & 31) == 0) wmax[r >> 5] = a;
    __syncthreads();
    if (r < 32) {
        float m = (r < 16) ? wmax[r] : 0.f;
#pragma unroll
        for (int o = 8; o; o >>= 1) m = fmaxf(m, __shfl_xor_sync(0xffffffffu, m, o));
        if (r == 0) wmax[0] = m;
    }
    __syncthreads();
    float s = fmaxf(wmax[0], 1e-30f);
    qa[(size_t)b * R_SZ + r] = __float2half_rn(acc / s);
    if (r == 0) sa[b] = s;
}

// ---------------------------------------------------------------------------
// MID kernel: fp16 single-pass GEMM, BM=64 x BN=512 (FULL row per CTA),
// Horner phi folding, fused per-row quantization epilogue (writes qa+sa
// in place — each CTA reads/writes only its own rows).
// 512 threads, warp grid 2x8 (warp tile 32x64). 3-stage x 64-k pipeline.
// ---------------------------------------------------------------------------
__global__ void __launch_bounds__(512, 1)
tt_mma_fused(__half* __restrict__ qa,
             float* __restrict__ sa,
             const __half* __restrict__ Bop,
             const float* __restrict__ z, int zcol) {
    constexpr int BM = 64, BN = 512;
    constexpr int MT = 2, NT = 8;            // warp tile 32x64
    constexpr int NWC = 8;                   // warp cols
    constexpr int SUB_A = BM * 64;           // 4KB
    constexpr int SUB_B = BN * 64;           // 32KB
    constexpr int SUBT  = SUB_A + SUB_B;
    constexpr int STAGE = 2 * SUBT;          // 72KB (64-k stage)
    constexpr int NSTAGE = 3;

    extern __shared__ __align__(16) char sm[];
    const uint32_t base = smem_u32(sm);

    const int tid = threadIdx.x, lane = tid & 31, wid = tid >> 5;
    const int m0 = blockIdx.y * BM;
    const int wm0 = (wid / NWC) * 32;        // warp row (0 or 32)
    const int wn0 = (wid % NWC) * 64;        // warp col
    const int wc  = wid % NWC;

    // per-lane z + input scale (rows r, r+8 per mt quad)
    float zA[MT], zB[MT], sA[MT], sB[MT];
#pragma unroll
    for (int mt = 0; mt < MT; mt++) {
        int rA = m0 + wm0 + mt * 16 + (lane >> 2);
        zA[mt] = z[(size_t)rA * D_SZ + zcol];
        zB[mt] = z[(size_t)(rA + 8) * D_SZ + zcol];
        sA[mt] = sa[rA];
        sB[mt] = sa[rA + 8];
    }

    float acc[MT][NT][4];
#pragma unroll
    for (int mt = 0; mt < MT; mt++)
#pragma unroll
        for (int nt = 0; nt < NT; nt++)
#pragma unroll
            for (int q = 0; q < 4; q++) acc[mt][nt][q] = 0.f;

    // produce one 64-k stage (2 sub-chunks), one commit group
    auto produce = [&](int cc) {
        const int s = cc % NSTAGE;
        const uint32_t stg = base + s * STAGE;
#pragma unroll
        for (int sub = 0; sub < 2; sub++) {
            const int sc = 2 * cc + sub;
            const int j  = (P_SZ - 1) - (sc >> 4);   // descending j
            const int rr = sc & 15;
            const uint32_t aS = stg + sub * SUBT;
            const uint32_t bS = aS + SUB_A;
            if (tid < BM * 4) {   // A: 256 transfers
                const int row = tid >> 2, c16 = tid & 3;
                const size_t go = (size_t)(m0 + row) * R_SZ + rr * KC + c16 * 8;
                CP_ASYNC16(aS + sw64(row, c16), qa + go);
            }
#pragma unroll
            for (int i = 0; i < (BN * 4) / 512; i++) {   // B: 2048 transfers
                const int idx = tid + i * 512;
                const int row = idx >> 2, c16 = idx & 3;
                const size_t go = (size_t)row * KTOT + j * R_SZ + rr * KC + c16 * 8;
                CP_ASYNC16(bS + sw64(row, c16), Bop + go);
            }
        }
        CP_COMMIT();
    };

    auto mma_stage = [&](int s) {
        const uint32_t stg = base + s * STAGE;
#pragma unroll
        for (int sub = 0; sub < 2; sub++) {
            const uint32_t aS = stg + sub * SUBT;
            const uint32_t bS = aS + SUB_A;
#pragma unroll
            for (int ks = 0; ks < 2; ks++) {
                uint32_t b[NT][2];
#pragma unroll
                for (int n2 = 0; n2 < NT / 2; n2++) {
                    const uint32_t rowb = wn0 + n2 * 16 + ((lane >> 4) << 3) + (lane & 7);
                    const uint32_t c16b = ((lane >> 3) & 1) + 2 * ks;
                    LDSM4(b[2 * n2][0], b[2 * n2][1], b[2 * n2 + 1][0], b[2 * n2 + 1][1],
                          bS + sw64(rowb, c16b));
                }
                uint32_t a[MT][4];
#pragma unroll
                for (int mt = 0; mt < MT; mt++) {
                    const uint32_t rowa = wm0 + mt * 16 + (lane & 15);
                    LDSM4(a[mt][0], a[mt][1], a[mt][2], a[mt][3],
                          aS + sw64(rowa, (lane >> 4) + 2 * ks));
                }
#pragma unroll
                for (int mt = 0; mt < MT; mt++)
#pragma unroll
                    for (int nt = 0; nt < NT; nt++) MMA_F16(acc[mt][nt], a[mt], b[nt]);
            }
        }
    };

    produce(0); produce(1);

    for (int c = 0; c < NCH2; c++) {
        CP_WAIT1();
        __syncthreads();
        if (c + 2 < NCH2) produce(c + 2); else CP_COMMIT();
        if (c && (c & 7) == 0) {
            // Horner: entering next-lower j — scale accumulators by z
#pragma unroll
            for (int mt = 0; mt < MT; mt++)
#pragma unroll
                for (int nt = 0; nt < NT; nt++) {
                    acc[mt][nt][0] *= zA[mt]; acc[mt][nt][1] *= zA[mt];
                    acc[mt][nt][2] *= zB[mt]; acc[mt][nt][3] *= zB[mt];
                }
        }
        mma_stage(c % NSTAGE);
    }

    // ---- fused epilogue: scale by input row-scale, quantize per output row ----
    // 1) apply input scale
#pragma unroll
    for (int mt = 0; mt < MT; mt++)
#pragma unroll
        for (int nt = 0; nt < NT; nt++) {
            acc[mt][nt][0] *= sA[mt]; acc[mt][nt][1] *= sA[mt];
            acc[mt][nt][2] *= sB[mt]; acc[mt][nt][3] *= sB[mt];
        }
    // 2) per-thread local row maxima (2 rows per mt: r and r+8)
    float lmax[MT][2];
#pragma unroll
    for (int mt = 0; mt < MT; mt++) {
        float m0v = 0.f, m1v = 0.f;
#pragma unroll
        for (int nt = 0; nt < NT; nt++) {
            m0v = fmaxf(m0v, fmaxf(fabsf(acc[mt][nt][0]), fabsf(acc[mt][nt][1])));
            m1v = fmaxf(m1v, fmaxf(fabsf(acc[mt][nt][2]), fabsf(acc[mt][nt][3])));
        }
        lmax[mt][0] = m0v; lmax[mt][1] = m1v;
    }
    // 3) reduce across the 4 lanes sharing each row (lane&3 varies)
#pragma unroll
    for (int mt = 0; mt < MT; mt++)
#pragma unroll
        for (int h = 0; h < 2; h++) {
            float v = lmax[mt][h];
            v = fmaxf(v, __shfl_xor_sync(0xffffffffu, v, 1));
            v = fmaxf(v, __shfl_xor_sync(0xffffffffu, v, 2));
            lmax[mt][h] = v;
        }
    // 4) cross-warp-column reduction via smem (reuse pipeline smem)
    __syncthreads();
    float* rmax = reinterpret_cast<float*>(sm);   // [64 rows][8 warpcols]
    if ((lane & 3) == 0) {
#pragma unroll
        for (int mt = 0; mt < MT; mt++) {
            rmax[(wm0 + mt * 16 + (lane >> 2)) * 8 + wc]     = lmax[mt][0];
            rmax[(wm0 + mt * 16 + 8 + (lane >> 2)) * 8 + wc] = lmax[mt][1];
        }
    }
    __syncthreads();
    // 5) final scale per row, write sa + qa
#pragma unroll
    for (int mt = 0; mt < MT; mt++)
#pragma unroll
        for (int h = 0; h < 2; h++) {
            const int rloc = wm0 + mt * 16 + h * 8 + (lane >> 2);
            float s = 1e-30f;
#pragma unroll
            for (int w = 0; w < 8; w++) s = fmaxf(s, rmax[rloc * 8 + w]);
            if (wc == 0 && (lane & 3) == 0) sa[m0 + rloc] = s;
            const float inv = 1.0f / s;
            const size_t rowoff = (size_t)(m0 + rloc) * R_SZ;
#pragma unroll
            for (int nt = 0; nt < NT; nt++) {
                __half2 hv;
                hv.x = __float2half_rn(acc[mt][nt][2 * h + 0] * inv);
                hv.y = __float2half_rn(acc[mt][nt][2 * h + 1] * inv);
                *reinterpret_cast<__half2*>(&qa[rowoff + wn0 + nt * 8 + (lane & 3) * 2]) = hv;
            }
        }
}

// ---------------------------------------------------------------------------
// LAST kernel: streaming single-pass GEMM (64x64), f32 output (R14 style).
// ---------------------------------------------------------------------------
__global__ void __launch_bounds__(256, 1)
tt_mma_last(const __half* __restrict__ Aop,
            const __half* __restrict__ Bop,
            const float* __restrict__ sa,
            const float* __restrict__ z, int zcol,
            float* __restrict__ outF, int Ntotal) {
    constexpr int BM = 64, BN = 64, MT = 2, NT = 2;   // 8 warps (2x4), tile 32x16
    constexpr int SUB_A = BM * 64;
    constexpr int SUB_B = BN * 64;
    constexpr int SUBT  = SUB_A + SUB_B;
    constexpr int STAGE = 2 * SUBT;
    constexpr int NSTAGE = 4;

    extern __shared__ __align__(16) char sm[];
    const uint32_t base = smem_u32(sm);

    const int tid = threadIdx.x, lane = tid & 31, wid = tid >> 5;
    const int m0 = blockIdx.y * BM, n0 = blockIdx.x * BN;
    const int wm0 = (wid >> 2) * 32;
    const int wn0 = (wid & 3) * 16;

    float zA[MT], zB[MT], sAr[MT], sBr[MT];
#pragma unroll
    for (int mt = 0; mt < MT; mt++) {
        int rA = m0 + wm0 + mt * 16 + (lane >> 2);
        zA[mt] = z[(size_t)rA * D_SZ + zcol];
        zB[mt] = z[(size_t)(rA + 8) * D_SZ + zcol];
        sAr[mt] = sa[rA];
        sBr[mt] = sa[rA + 8];
    }

    float acc[MT][NT][4];
#pragma unroll
    for (int mt = 0; mt < MT; mt++)
#pragma unroll
        for (int nt = 0; nt < NT; nt++)
#pragma unroll
            for (int q = 0; q < 4; q++) acc[mt][nt][q] = 0.f;

    auto produce = [&](int cc) {
        const int s = cc & (NSTAGE - 1);
        const uint32_t stg = base + s * STAGE;
#pragma unroll
        for (int sub = 0; sub < 2; sub++) {
            const int sc = 2 * cc + sub;
            const int j  = (P_SZ - 1) - (sc >> 4);
            const int rr = sc & 15;
            const uint32_t aS = stg + sub * SUBT;
            const uint32_t bS = aS + SUB_A;
            const int row = tid >> 2, c16 = tid & 3;   // 256 threads = BM*4
            const uint32_t off = sw64(row, c16);
            const size_t ga = (size_t)(m0 + row) * R_SZ + rr * KC + c16 * 8;
            CP_ASYNC16(aS + off, Aop + ga);
            const size_t gb = (size_t)(n0 + row) * KTOT + j * R_SZ + rr * KC + c16 * 8;
            CP_ASYNC16(bS + off, Bop + gb);
        }
        CP_COMMIT();
    };

    auto mma_stage = [&](int s) {
        const uint32_t stg = base + s * STAGE;
#pragma unroll
        for (int sub = 0; sub < 2; sub++) {
            const uint32_t aS = stg + sub * SUBT;
            const uint32_t bS = aS + SUB_A;
#pragma unroll
            for (int ks = 0; ks < 2; ks++) {
                uint32_t b[NT][2];
                {
                    const uint32_t rowb = wn0 + ((lane >> 4) << 3) + (lane & 7);
                    const uint32_t c16b = ((lane >> 3) & 1) + 2 * ks;
                    LDSM4(b[0][0], b[0][1], b[1][0], b[1][1], bS + sw64(rowb, c16b));
                }
                uint32_t a[MT][4];
#pragma unroll
                for (int mt = 0; mt < MT; mt++) {
                    const uint32_t rowa = wm0 + mt * 16 + (lane & 15);
                    LDSM4(a[mt][0], a[mt][1], a[mt][2], a[mt][3],
                          aS + sw64(rowa, (lane >> 4) + 2 * ks));
                }
#pragma unroll
                for (int mt = 0; mt < MT; mt++)
#pragma unroll
                    for (int nt = 0; nt < NT; nt++) MMA_F16(acc[mt][nt], a[mt], b[nt]);
            }
        }
    };

    produce(0); produce(1); produce(2);

    for (int c = 0; c < NCH2; c++) {
        CP_WAIT2();
        __syncthreads();
        if (c + 3 < NCH2) produce(c + 3); else CP_COMMIT();
        if (c && (c & 7) == 0) {
#pragma unroll
            for (int mt = 0; mt < MT; mt++)
#pragma unroll
                for (int nt = 0; nt < NT; nt++) {
                    acc[mt][nt][0] *= zA[mt]; acc[mt][nt][1] *= zA[mt];
                    acc[mt][nt][2] *= zB[mt]; acc[mt][nt][3] *= zB[mt];
                }
        }
        mma_stage(c & (NSTAGE - 1));
    }

#pragma unroll
    for (int mt = 0; mt < MT; mt++) {
        const int row0 = m0 + wm0 + mt * 16 + (lane >> 2);
#pragma unroll
        for (int nt = 0; nt < NT; nt++) {
            const int col = n0 + wn0 + nt * 8 + (lane & 3) * 2;
            *reinterpret_cast<float2*>(&outF[(size_t)row0 * Ntotal + col]) =
                make_float2(acc[mt][nt][0] * sAr[mt], acc[mt][nt][1] * sAr[mt]);
            *reinterpret_cast<float2*>(&outF[(size_t)(row0 + 8) * Ntotal + col]) =
                make_float2(acc[mt][nt][2] * sBr[mt], acc[mt][nt][3] * sBr[mt]);
        }
    }
}

// ---------------------------------------------------------------------------
// Launch (graph-capturable, allocation-free)
// Inputs: z [B,D] f32, G0 [P,R] f32, G_mid [6,R,P,R] f32, G_last [R,P,OUT] f32, t
// Output: [B, OUT] f32
// ---------------------------------------------------------------------------
extern "C" void kernel_launch(void* const* d_in, const int* in_sizes, int n_in,
                              void* d_out, int out_size) {
    (void)in_sizes; (void)n_in; (void)out_size;
    const float* z     = (const float*)d_in[0];
    const float* G0    = (const float*)d_in[1];
    const float* Gmid  = (const float*)d_in[2];
    const float* Glast = (const float*)d_in[3];
    float* out = (float*)d_out;

    float *p_tg0, *p_sa;
    __half *p_qa, *p_bm, *p_bl;
    cudaGetSymbolAddress((void**)&p_tg0, g_tanh_g0);
    cudaGetSymbolAddress((void**)&p_sa,  g_sa);
    cudaGetSymbolAddress((void**)&p_qa,  g_qa);
    cudaGetSymbolAddress((void**)&p_bm,  g_b_mid);
    cudaGetSymbolAddress((void**)&p_bl,  g_b_last);

    const int SMEM_MID  = 3 * 2 * (64 + 512) * 64;   // 221184 (216 KB)
    const int SMEM_LAST = 4 * 2 * (64 + 64) * 64;    // 65536
    cudaFuncSetAttribute((const void*)tt_mma_fused,
                         cudaFuncAttributeMaxDynamicSharedMemorySize, SMEM_MID);
    cudaFuncSetAttribute((const void*)tt_mma_last,
                         cudaFuncAttributeMaxDynamicSharedMemorySize, SMEM_LAST);

    // precompute
    tanh_small_kernel<<<(P_SZ * R_SZ + 255) / 256, 256>>>(G0, p_tg0, P_SZ * R_SZ);
    trans_f16_kernel<<<dim3(R_SZ / 32, R_SZ / 32, NMID * P_SZ), dim3(32, 8)>>>(
        Gmid, p_bm, R_SZ, (size_t)R_SZ * P_SZ * R_SZ, (size_t)R_SZ * KTOT);
    trans_f16_kernel<<<dim3(R_SZ / 32, OUT_SZ / 32, P_SZ), dim3(32, 8)>>>(
        Glast, p_bl, OUT_SZ, 0, 0);

    // first core with fused quantization
    first_core_quant_kernel<<<B_SZ, R_SZ>>>(z, p_qa, p_sa);

    // six middle cores: GEMM with fused in-place quantization epilogue
    for (int i = 0; i < NMID; i++) {
        tt_mma_fused<<<dim3(1, B_SZ / 64), 512, SMEM_MID>>>(
            p_qa, p_sa, p_bm + (size_t)i * R_SZ * KTOT, z, i + 1);
    }

    // last core -> d_out [B, OUT] f32
    tt_mma_last<<<dim3(1, B_SZ / 64), 256, SMEM_LAST>>>(
        p_qa, p_bl, p_sa, z, D_SZ - 1, out, OUT_SZ);
}

// round 16
// speedup vs baseline: 1.0858x; 1.0858x over previous
#include <cuda_runtime.h>
#include <cuda_fp16.h>
#include <cstdint>
#include <cstddef>

// ---------------------------------------------------------------------------
// Problem constants
// ---------------------------------------------------------------------------
#define B_SZ   8192
#define D_SZ   8
#define P_SZ   10
#define R_SZ   512
#define OUT_SZ 64
#define NMID   6
#define KTOT   (P_SZ * R_SZ)       // 5120
#define KC     32                  // K per SUB-chunk
#define NCH2   (KTOT / (2 * KC))   // 80 big chunks (64 k each)

// ---------------------------------------------------------------------------
// Device-global scratch
// ---------------------------------------------------------------------------
__device__ float  g_tanh_g0[P_SZ * R_SZ];
__device__ float  g_resf[(size_t)B_SZ * R_SZ];    // f32 master res between layers
__device__ __half g_qa[(size_t)B_SZ * R_SZ];      // fp16 of res/s (per-row scaled)
__device__ float  g_sa[B_SZ];                     // per-row scale
// B operands: tanh'd, transposed to [n][k=j*512+r], single fp16 (|tanh|<=0.1)
__device__ __half g_b_mid[(size_t)NMID * R_SZ * KTOT];
__device__ __half g_b_last[(size_t)OUT_SZ * KTOT];

// ---------------------------------------------------------------------------
// PTX helpers (sm_80-era: cp.async, ldmatrix, mma.sync — NO tcgen05)
// ---------------------------------------------------------------------------
__device__ __forceinline__ uint32_t smem_u32(const void* p) {
    uint32_t a;
    asm("{ .reg .u64 t; cvta.to.shared.u64 t, %1; cvt.u32.u64 %0, t; }" : "=r"(a) : "l"(p));
    return a;
}
#define CP_ASYNC16(dst, src) \
    asm volatile("cp.async.cg.shared.global [%0], [%1], 16;" :: "r"(dst), "l"(src) : "memory")
#define CP_COMMIT() asm volatile("cp.async.commit_group;" ::: "memory")
#define CP_WAIT1()  asm volatile("cp.async.wait_group 1;" ::: "memory")
#define CP_WAIT2()  asm volatile("cp.async.wait_group 2;" ::: "memory")

#define LDSM4(r0, r1, r2, r3, addr) \
    asm volatile("ldmatrix.sync.aligned.m8n8.x4.shared.b16 {%0,%1,%2,%3}, [%4];" \
                 : "=r"(r0), "=r"(r1), "=r"(r2), "=r"(r3) : "r"(addr))

#define MMA_F16(d, a, b) \
    asm volatile("mma.sync.aligned.m16n8k16.row.col.f32.f16.f16.f32 " \
                 "{%0,%1,%2,%3}, {%4,%5,%6,%7}, {%8,%9}, {%0,%1,%2,%3};" \
                 : "+f"((d)[0]), "+f"((d)[1]), "+f"((d)[2]), "+f"((d)[3]) \
                 : "r"((a)[0]), "r"((a)[1]), "r"((a)[2]), "r"((a)[3]), \
                   "r"((b)[0]), "r"((b)[1]))

// 64B-row XOR swizzle: conflict-free across all 8-row ldmatrix phases.
__device__ __forceinline__ uint32_t sw64(uint32_t row, uint32_t c16) {
    return row * 64u + ((c16 ^ ((row >> 1) & 3u)) << 4);
}

// ---------------------------------------------------------------------------
// Precompute: tanh + transpose -> single fp16
//   G [R, P, N] (n contiguous) -> B [n][j*512 + r] (k contiguous)
// ---------------------------------------------------------------------------
__global__ void trans_f16_kernel(const float* __restrict__ G,
                                 __half* __restrict__ bo,
                                 int N, size_t gStride, size_t oStride) {
    __shared__ float t[32][33];
    int layer = blockIdx.z / P_SZ;
    int j     = blockIdx.z % P_SZ;
    const float* Gp = G + (size_t)layer * gStride;
    __half* bop = bo + (size_t)layer * oStride;
    int rt = blockIdx.x * 32, nt = blockIdx.y * 32;
    int tx = threadIdx.x, ty = threadIdx.y;   // block (32, 8)
#pragma unroll
    for (int yy = ty; yy < 32; yy += 8)
        t[yy][tx] = tanhf(Gp[((size_t)(rt + yy) * P_SZ + j) * N + nt + tx]);
    __syncthreads();
#pragma unroll
    for (int yy = ty; yy < 32; yy += 8) {
        int n = nt + yy, r = rt + tx;
        bop[(size_t)n * KTOT + (size_t)j * R_SZ + r] = __float2half_rn(t[tx][yy]);
    }
}

__global__ void tanh_small_kernel(const float* __restrict__ src,
                                  float* __restrict__ dst, int n) {
    int i = blockIdx.x * blockDim.x + threadIdx.x;
    if (i < n) dst[i] = tanhf(src[i]);
}

// First core -> f32 res
__global__ void first_core_kernel(const float* __restrict__ z,
                                  float* __restrict__ resf) {
    int b = blockIdx.x;
    int r = threadIdx.x;
    float zv = z[b * D_SZ + 0];
    float ph = 1.f, acc = 0.f;
#pragma unroll
    for (int j = 0; j < P_SZ; j++) {
        acc += g_tanh_g0[j * R_SZ + r] * ph;
        ph *= zv;
    }
    resf[(size_t)b * R_SZ + r] = acc;
}

// Per-row quantize (vectorized): 128 threads/row, float4 loads.
//   s = rowmax |x|; A = fp16(x/s)
__global__ void quant_res_kernel(const float* __restrict__ resf,
                                 __half* __restrict__ qa,
                                 float* __restrict__ sa) {
    __shared__ float wmax[4];
    int b = blockIdx.x, tid = threadIdx.x;   // 128 threads
    float4 v = *reinterpret_cast<const float4*>(&resf[(size_t)b * R_SZ + tid * 4]);
    float a = fmaxf(fmaxf(fabsf(v.x), fabsf(v.y)), fmaxf(fabsf(v.z), fabsf(v.w)));
#pragma unroll
    for (int o = 16; o; o >>= 1) a = fmaxf(a, __shfl_xor_sync(0xffffffffu, a, o));
    if ((tid & 31) == 0) wmax[tid >> 5] = a;
    __syncthreads();
    float m = fmaxf(fmaxf(wmax[0], wmax[1]), fmaxf(wmax[2], wmax[3]));
    float s = fmaxf(m, 1e-30f);
    float inv = 1.0f / s;
    __half2 h0, h1;
    h0.x = __float2half_rn(v.x * inv); h0.y = __float2half_rn(v.y * inv);
    h1.x = __float2half_rn(v.z * inv); h1.y = __float2half_rn(v.w * inv);
    uint2 packed;
    packed.x = *reinterpret_cast<uint32_t*>(&h0);
    packed.y = *reinterpret_cast<uint32_t*>(&h1);
    *reinterpret_cast<uint2*>(&qa[(size_t)b * R_SZ + tid * 4]) = packed;
    if (tid == 0) sa[b] = s;
}

// ---------------------------------------------------------------------------
// HMMA fp16 single-pass GEMM, 64-k (2 sub-chunk) stages, Horner phi folding:
//   out[m,n] = sA[m] * sum_{j desc} ( acc*z_m + sum_r A[m,r] B_j[r,n] )
// MINCTAS CTAs co-resident per SM; NSTAGE-deep cp.async ring.
// Warp tile WM x WN (64x64 for mids: fewer LDSM per MMA).
// ---------------------------------------------------------------------------
template<int BM, int BN, int WM, int WN, int THREADS, int MINCTAS, int NSTAGE>
__global__ void __launch_bounds__(THREADS, MINCTAS)
tt_mma_kernel(const __half* __restrict__ Aop,
              const __half* __restrict__ Bop,
              const float* __restrict__ sa,
              const float* __restrict__ z, int zcol,
              float* __restrict__ outF, int Ntotal) {
    constexpr int MT = WM / 16, NT = WN / 8;
    constexpr int SUB_A = BM * 64;             // A bytes per sub-chunk
    constexpr int SUB_B = BN * 64;
    constexpr int SUBT  = SUB_A + SUB_B;
    constexpr int STAGE = 2 * SUBT;            // 64-k stage

    extern __shared__ __align__(16) char sm[];
    const uint32_t base = smem_u32(sm);

    const int tid = threadIdx.x, lane = tid & 31, wid = tid >> 5;
    const int m0 = blockIdx.y * BM, n0 = blockIdx.x * BN;
    constexpr int NWC = BN / WN;
    const int wm0 = (wid / NWC) * WM;
    const int wn0 = (wid % NWC) * WN;

    // per-lane z + scale (rows r, r+8 per mt quad)
    float zA[MT], zB[MT], sA[MT], sB[MT];
#pragma unroll
    for (int mt = 0; mt < MT; mt++) {
        int rA = m0 + wm0 + mt * 16 + (lane >> 2);
        zA[mt] = z[(size_t)rA * D_SZ + zcol];
        zB[mt] = z[(size_t)(rA + 8) * D_SZ + zcol];
        sA[mt] = sa[rA];
        sB[mt] = sa[rA + 8];
    }

    float acc[MT][NT][4];
#pragma unroll
    for (int mt = 0; mt < MT; mt++)
#pragma unroll
        for (int nt = 0; nt < NT; nt++)
#pragma unroll
            for (int q = 0; q < 4; q++) acc[mt][nt][q] = 0.f;

    // produce one 64-k stage (2 sub-chunks), one commit group
    auto produce = [&](int cc) {
        const int s = cc % NSTAGE;
        const uint32_t stg = base + s * STAGE;
#pragma unroll
        for (int sub = 0; sub < 2; sub++) {
            const int sc = 2 * cc + sub;
            const int j  = (P_SZ - 1) - (sc >> 4);   // descending j
            const int rr = sc & 15;
            const uint32_t aS = stg + sub * SUBT;
            const uint32_t bS = aS + SUB_A;
#pragma unroll
            for (int i = 0; i < (BM * 4) / THREADS; i++) {
                const int idx = tid + i * THREADS;
                const int row = idx >> 2, c16 = idx & 3;
                const uint32_t off = sw64(row, c16);
                const size_t go = (size_t)(m0 + row) * R_SZ + rr * KC + c16 * 8;
                CP_ASYNC16(aS + off, Aop + go);
            }
#pragma unroll
            for (int i = 0; i < (BN * 4) / THREADS; i++) {
                const int idx = tid + i * THREADS;
                const int row = idx >> 2, c16 = idx & 3;
                const uint32_t off = sw64(row, c16);
                const size_t go = (size_t)(n0 + row) * KTOT + j * R_SZ + rr * KC + c16 * 8;
                CP_ASYNC16(bS + off, Bop + go);
            }
        }
        CP_COMMIT();
    };

    auto mma_stage = [&](int s) {
        const uint32_t stg = base + s * STAGE;
#pragma unroll
        for (int sub = 0; sub < 2; sub++) {
            const uint32_t aS = stg + sub * SUBT;
            const uint32_t bS = aS + SUB_A;
#pragma unroll
            for (int ks = 0; ks < 2; ks++) {
                uint32_t b[NT][2];
#pragma unroll
                for (int n2 = 0; n2 < NT / 2; n2++) {
                    const uint32_t rowb = wn0 + n2 * 16 + ((lane >> 4) << 3) + (lane & 7);
                    const uint32_t c16b = ((lane >> 3) & 1) + 2 * ks;
                    LDSM4(b[2 * n2][0], b[2 * n2][1], b[2 * n2 + 1][0], b[2 * n2 + 1][1],
                          bS + sw64(rowb, c16b));
                }
                uint32_t a[MT][4];
#pragma unroll
                for (int mt = 0; mt < MT; mt++) {
                    const uint32_t rowa = wm0 + mt * 16 + (lane & 15);
                    LDSM4(a[mt][0], a[mt][1], a[mt][2], a[mt][3],
                          aS + sw64(rowa, (lane >> 4) + 2 * ks));
                }
#pragma unroll
                for (int mt = 0; mt < MT; mt++)
#pragma unroll
                    for (int nt = 0; nt < NT; nt++) MMA_F16(acc[mt][nt], a[mt], b[nt]);
            }
        }
    };

    // prologue: NSTAGE-1 stages in flight
#pragma unroll
    for (int p = 0; p < NSTAGE - 1; p++) produce(p);

    for (int c = 0; c < NCH2; c++) {
        if constexpr (NSTAGE == 3) CP_WAIT1(); else CP_WAIT2();
        __syncthreads();
        if (c + NSTAGE - 1 < NCH2) produce(c + NSTAGE - 1); else CP_COMMIT();
        if (c && (c & 7) == 0) {
            // Horner: entering next-lower j — scale accumulators by z
#pragma unroll
            for (int mt = 0; mt < MT; mt++)
#pragma unroll
                for (int nt = 0; nt < NT; nt++) {
                    acc[mt][nt][0] *= zA[mt]; acc[mt][nt][1] *= zA[mt];
                    acc[mt][nt][2] *= zB[mt]; acc[mt][nt][3] *= zB[mt];
                }
        }
        mma_stage(c % NSTAGE);
    }

    // epilogue: apply per-row scale, write f32
#pragma unroll
    for (int mt = 0; mt < MT; mt++) {
        const int row0 = m0 + wm0 + mt * 16 + (lane >> 2);
#pragma unroll
        for (int nt = 0; nt < NT; nt++) {
            const int col = n0 + wn0 + nt * 8 + (lane & 3) * 2;
            *reinterpret_cast<float2*>(&outF[(size_t)row0 * Ntotal + col]) =
                make_float2(acc[mt][nt][0] * sA[mt], acc[mt][nt][1] * sA[mt]);
            *reinterpret_cast<float2*>(&outF[(size_t)(row0 + 8) * Ntotal + col]) =
                make_float2(acc[mt][nt][2] * sB[mt], acc[mt][nt][3] * sB[mt]);
        }
    }
}

// ---------------------------------------------------------------------------
// Launch (graph-capturable, allocation-free)
// Inputs: z [B,D] f32, G0 [P,R] f32, G_mid [6,R,P,R] f32, G_last [R,P,OUT] f32, t
// Output: [B, OUT] f32
// ---------------------------------------------------------------------------
extern "C" void kernel_launch(void* const* d_in, const int* in_sizes, int n_in,
                              void* d_out, int out_size) {
    (void)in_sizes; (void)n_in; (void)out_size;
    const float* z     = (const float*)d_in[0];
    const float* G0    = (const float*)d_in[1];
    const float* Gmid  = (const float*)d_in[2];
    const float* Glast = (const float*)d_in[3];
    float* out = (float*)d_out;

    float *p_tg0, *p_resf, *p_sa;
    __half *p_qa, *p_bm, *p_bl;
    cudaGetSymbolAddress((void**)&p_tg0,  g_tanh_g0);
    cudaGetSymbolAddress((void**)&p_resf, g_resf);
    cudaGetSymbolAddress((void**)&p_sa,   g_sa);
    cudaGetSymbolAddress((void**)&p_qa,   g_qa);
    cudaGetSymbolAddress((void**)&p_bm,   g_b_mid);
    cudaGetSymbolAddress((void**)&p_bl,   g_b_last);

    // mids: 3 stages x 2 subs x (128+128)*64 = 98304 B/CTA -> 2 CTAs/SM
    const int SMEM_MID  = 3 * 2 * (128 + 128) * 64;  // 98304
    const int SMEM_LAST = 4 * 2 * (64 + 64) * 64;    // 65536
    cudaFuncSetAttribute((const void*)tt_mma_kernel<128, 128, 64, 64, 128, 2, 3>,
                         cudaFuncAttributeMaxDynamicSharedMemorySize, SMEM_MID);
    cudaFuncSetAttribute((const void*)tt_mma_kernel<64, 64, 32, 16, 256, 1, 4>,
                         cudaFuncAttributeMaxDynamicSharedMemorySize, SMEM_LAST);

    // precompute
    tanh_small_kernel<<<(P_SZ * R_SZ + 255) / 256, 256>>>(G0, p_tg0, P_SZ * R_SZ);
    trans_f16_kernel<<<dim3(R_SZ / 32, R_SZ / 32, NMID * P_SZ), dim3(32, 8)>>>(
        Gmid, p_bm, R_SZ, (size_t)R_SZ * P_SZ * R_SZ, (size_t)R_SZ * KTOT);
    trans_f16_kernel<<<dim3(R_SZ / 32, OUT_SZ / 32, P_SZ), dim3(32, 8)>>>(
        Glast, p_bl, OUT_SZ, 0, 0);

    // first core -> f32 res -> quantize
    first_core_kernel<<<B_SZ, R_SZ>>>(z, p_resf);
    quant_res_kernel<<<B_SZ, 128>>>(p_resf, p_qa, p_sa);

    // six middle cores: GEMM (f32 out) + per-row quantize — 256 CTAs, 2/SM,
    // 128 threads/CTA with 64x64 warp tiles (half the LDSM issue per MMA).
    for (int i = 0; i < NMID; i++) {
        tt_mma_kernel<128, 128, 64, 64, 128, 2, 3>
            <<<dim3(R_SZ / 128, B_SZ / 128), 128, SMEM_MID>>>(
            p_qa, p_bm + (size_t)i * R_SZ * KTOT, p_sa,
            z, i + 1, p_resf, R_SZ);
        quant_res_kernel<<<B_SZ, 128>>>(p_resf, p_qa, p_sa);
    }

    // last core -> d_out [B, OUT] f32
    tt_mma_kernel<64, 64, 32, 16, 256, 1, 4><<<dim3(1, B_SZ / 64), 256, SMEM_LAST>>>(
        p_qa, p_bl, p_sa, z, D_SZ - 1, out, OUT_SZ);
}

// round 17
// speedup vs baseline: 1.1014x; 1.0143x over previous
#include <cuda_runtime.h>
#include <cuda_fp16.h>
#include <cstdint>
#include <cstddef>

// ---------------------------------------------------------------------------
// Problem constants
// ---------------------------------------------------------------------------
#define B_SZ   8192
#define D_SZ   8
#define P_SZ   10
#define R_SZ   512
#define OUT_SZ 64
#define NMID   6
#define KTOT   (P_SZ * R_SZ)       // 5120
#define KC     32                  // K per SUB-chunk
#define NCH2   (KTOT / (2 * KC))   // 80 big chunks (64 k each)

// ---------------------------------------------------------------------------
// Device-global scratch
// ---------------------------------------------------------------------------
__device__ float  g_tanh_g0[P_SZ * R_SZ];
__device__ float  g_resf[(size_t)B_SZ * R_SZ];    // f32 master res between layers
__device__ __half g_qa[(size_t)B_SZ * R_SZ];      // fp16 of res/s (per-row scaled)
__device__ float  g_sa[B_SZ];                     // per-row scale
// B operands: tanh'd, transposed to [n][k=j*512+r], single fp16 (|tanh|<=0.1)
__device__ __half g_b_mid[(size_t)NMID * R_SZ * KTOT];
__device__ __half g_b_last[(size_t)OUT_SZ * KTOT];

// ---------------------------------------------------------------------------
// PTX helpers (sm_80-era: cp.async, ldmatrix, mma.sync — NO tcgen05)
// ---------------------------------------------------------------------------
__device__ __forceinline__ uint32_t smem_u32(const void* p) {
    uint32_t a;
    asm("{ .reg .u64 t; cvta.to.shared.u64 t, %1; cvt.u32.u64 %0, t; }" : "=r"(a) : "l"(p));
    return a;
}
#define CP_ASYNC16(dst, src) \
    asm volatile("cp.async.cg.shared.global [%0], [%1], 16;" :: "r"(dst), "l"(src) : "memory")
#define CP_COMMIT() asm volatile("cp.async.commit_group;" ::: "memory")
#define CP_WAIT1()  asm volatile("cp.async.wait_group 1;" ::: "memory")
#define CP_WAIT2()  asm volatile("cp.async.wait_group 2;" ::: "memory")

#define LDSM4(r0, r1, r2, r3, addr) \
    asm volatile("ldmatrix.sync.aligned.m8n8.x4.shared.b16 {%0,%1,%2,%3}, [%4];" \
                 : "=r"(r0), "=r"(r1), "=r"(r2), "=r"(r3) : "r"(addr))

#define MMA_F16(d, a, b) \
    asm volatile("mma.sync.aligned.m16n8k16.row.col.f32.f16.f16.f32 " \
                 "{%0,%1,%2,%3}, {%4,%5,%6,%7}, {%8,%9}, {%0,%1,%2,%3};" \
                 : "+f"((d)[0]), "+f"((d)[1]), "+f"((d)[2]), "+f"((d)[3]) \
                 : "r"((a)[0]), "r"((a)[1]), "r"((a)[2]), "r"((a)[3]), \
                   "r"((b)[0]), "r"((b)[1]))

// 64B-row XOR swizzle: conflict-free across all 8-row ldmatrix phases.
__device__ __forceinline__ uint32_t sw64(uint32_t row, uint32_t c16) {
    return row * 64u + ((c16 ^ ((row >> 1) & 3u)) << 4);
}

// Fast tanh: 1 - 2/(e^{2x}+1). |err| ~1e-6 — far below fp16 quantization.
// Saturates correctly (expf overflow -> 1, underflow -> -1).
__device__ __forceinline__ float tanh_fast(float x) {
    float e = __expf(2.0f * x);
    return 1.0f - 2.0f / (e + 1.0f);
}

// ---------------------------------------------------------------------------
// Precompute: tanh + transpose -> single fp16
//   G [R, P, N] (n contiguous) -> B [n][j*512 + r] (k contiguous)
// ---------------------------------------------------------------------------
__global__ void trans_f16_kernel(const float* __restrict__ G,
                                 __half* __restrict__ bo,
                                 int N, size_t gStride, size_t oStride) {
    __shared__ float t[32][33];
    int layer = blockIdx.z / P_SZ;
    int j     = blockIdx.z % P_SZ;
    const float* Gp = G + (size_t)layer * gStride;
    __half* bop = bo + (size_t)layer * oStride;
    int rt = blockIdx.x * 32, nt = blockIdx.y * 32;
    int tx = threadIdx.x, ty = threadIdx.y;   // block (32, 8)
#pragma unroll
    for (int yy = ty; yy < 32; yy += 8)
        t[yy][tx] = tanh_fast(Gp[((size_t)(rt + yy) * P_SZ + j) * N + nt + tx]);
    __syncthreads();
#pragma unroll
    for (int yy = ty; yy < 32; yy += 8) {
        int n = nt + yy, r = rt + tx;
        bop[(size_t)n * KTOT + (size_t)j * R_SZ + r] = __float2half_rn(t[tx][yy]);
    }
}

__global__ void tanh_small_kernel(const float* __restrict__ src,
                                  float* __restrict__ dst, int n) {
    int i = blockIdx.x * blockDim.x + threadIdx.x;
    if (i < n) dst[i] = tanh_fast(src[i]);
}

// First core + fused per-row quantization: qa/sa written directly.
__global__ void first_core_quant_kernel(const float* __restrict__ z,
                                        __half* __restrict__ qa,
                                        float* __restrict__ sa) {
    __shared__ float wmax[16];
    int b = blockIdx.x;
    int r = threadIdx.x;     // 512 threads
    float zv = z[b * D_SZ + 0];
    float ph = 1.f, acc = 0.f;
#pragma unroll
    for (int j = 0; j < P_SZ; j++) {
        acc += g_tanh_g0[j * R_SZ + r] * ph;
        ph *= zv;
    }
    float a = fabsf(acc);
#pragma unroll
    for (int o = 16; o; o >>= 1) a = fmaxf(a, __shfl_xor_sync(0xffffffffu, a, o));
    if ((r & 31) == 0) wmax[r >> 5] = a;
    __syncthreads();
    if (r < 32) {
        float m = (r < 16) ? wmax[r] : 0.f;
#pragma unroll
        for (int o = 8; o; o >>= 1) m = fmaxf(m, __shfl_xor_sync(0xffffffffu, m, o));
        if (r == 0) wmax[0] = m;
    }
    __syncthreads();
    float s = fmaxf(wmax[0], 1e-30f);
    qa[(size_t)b * R_SZ + r] = __float2half_rn(acc / s);
    if (r == 0) sa[b] = s;
}

// Per-row quantize (vectorized): 128 threads/row, float4 loads.
//   s = rowmax |x|; A = fp16(x/s)
__global__ void quant_res_kernel(const float* __restrict__ resf,
                                 __half* __restrict__ qa,
                                 float* __restrict__ sa) {
    __shared__ float wmax[4];
    int b = blockIdx.x, tid = threadIdx.x;   // 128 threads
    float4 v = *reinterpret_cast<const float4*>(&resf[(size_t)b * R_SZ + tid * 4]);
    float a = fmaxf(fmaxf(fabsf(v.x), fabsf(v.y)), fmaxf(fabsf(v.z), fabsf(v.w)));
#pragma unroll
    for (int o = 16; o; o >>= 1) a = fmaxf(a, __shfl_xor_sync(0xffffffffu, a, o));
    if ((tid & 31) == 0) wmax[tid >> 5] = a;
    __syncthreads();
    float m = fmaxf(fmaxf(wmax[0], wmax[1]), fmaxf(wmax[2], wmax[3]));
    float s = fmaxf(m, 1e-30f);
    float inv = 1.0f / s;
    __half2 h0, h1;
    h0.x = __float2half_rn(v.x * inv); h0.y = __float2half_rn(v.y * inv);
    h1.x = __float2half_rn(v.z * inv); h1.y = __float2half_rn(v.w * inv);
    uint2 packed;
    packed.x = *reinterpret_cast<uint32_t*>(&h0);
    packed.y = *reinterpret_cast<uint32_t*>(&h1);
    *reinterpret_cast<uint2*>(&qa[(size_t)b * R_SZ + tid * 4]) = packed;
    if (tid == 0) sa[b] = s;
}

// ---------------------------------------------------------------------------
// HMMA fp16 single-pass GEMM, 64-k (2 sub-chunk) stages, Horner phi folding:
//   out[m,n] = sA[m] * sum_{j desc} ( acc*z_m + sum_r A[m,r] B_j[r,n] )
// MINCTAS CTAs co-resident per SM; NSTAGE-deep cp.async ring.
// ---------------------------------------------------------------------------
template<int BM, int BN, int WM, int WN, int THREADS, int MINCTAS, int NSTAGE>
__global__ void __launch_bounds__(THREADS, MINCTAS)
tt_mma_kernel(const __half* __restrict__ Aop,
              const __half* __restrict__ Bop,
              const float* __restrict__ sa,
              const float* __restrict__ z, int zcol,
              float* __restrict__ outF, int Ntotal) {
    constexpr int MT = WM / 16, NT = WN / 8;
    constexpr int SUB_A = BM * 64;             // A bytes per sub-chunk
    constexpr int SUB_B = BN * 64;
    constexpr int SUBT  = SUB_A + SUB_B;
    constexpr int STAGE = 2 * SUBT;            // 64-k stage

    extern __shared__ __align__(16) char sm[];
    const uint32_t base = smem_u32(sm);

    const int tid = threadIdx.x, lane = tid & 31, wid = tid >> 5;
    const int m0 = blockIdx.y * BM, n0 = blockIdx.x * BN;
    constexpr int NWC = BN / WN;
    const int wm0 = (wid / NWC) * WM;
    const int wn0 = (wid % NWC) * WN;

    // per-lane z + scale (rows r, r+8 per mt quad)
    float zA[MT], zB[MT], sA[MT], sB[MT];
#pragma unroll
    for (int mt = 0; mt < MT; mt++) {
        int rA = m0 + wm0 + mt * 16 + (lane >> 2);
        zA[mt] = z[(size_t)rA * D_SZ + zcol];
        zB[mt] = z[(size_t)(rA + 8) * D_SZ + zcol];
        sA[mt] = sa[rA];
        sB[mt] = sa[rA + 8];
    }

    float acc[MT][NT][4];
#pragma unroll
    for (int mt = 0; mt < MT; mt++)
#pragma unroll
        for (int nt = 0; nt < NT; nt++)
#pragma unroll
            for (int q = 0; q < 4; q++) acc[mt][nt][q] = 0.f;

    // produce one 64-k stage (2 sub-chunks), one commit group
    auto produce = [&](int cc) {
        const int s = cc % NSTAGE;
        const uint32_t stg = base + s * STAGE;
#pragma unroll
        for (int sub = 0; sub < 2; sub++) {
            const int sc = 2 * cc + sub;
            const int j  = (P_SZ - 1) - (sc >> 4);   // descending j
            const int rr = sc & 15;
            const uint32_t aS = stg + sub * SUBT;
            const uint32_t bS = aS + SUB_A;
#pragma unroll
            for (int i = 0; i < (BM * 4) / THREADS; i++) {
                const int idx = tid + i * THREADS;
                const int row = idx >> 2, c16 = idx & 3;
                const uint32_t off = sw64(row, c16);
                const size_t go = (size_t)(m0 + row) * R_SZ + rr * KC + c16 * 8;
                CP_ASYNC16(aS + off, Aop + go);
            }
#pragma unroll
            for (int i = 0; i < (BN * 4) / THREADS; i++) {
                const int idx = tid + i * THREADS;
                const int row = idx >> 2, c16 = idx & 3;
                const uint32_t off = sw64(row, c16);
                const size_t go = (size_t)(n0 + row) * KTOT + j * R_SZ + rr * KC + c16 * 8;
                CP_ASYNC16(bS + off, Bop + go);
            }
        }
        CP_COMMIT();
    };

    auto mma_stage = [&](int s) {
        const uint32_t stg = base + s * STAGE;
#pragma unroll
        for (int sub = 0; sub < 2; sub++) {
            const uint32_t aS = stg + sub * SUBT;
            const uint32_t bS = aS + SUB_A;
#pragma unroll
            for (int ks = 0; ks < 2; ks++) {
                uint32_t b[NT][2];
#pragma unroll
                for (int n2 = 0; n2 < NT / 2; n2++) {
                    const uint32_t rowb = wn0 + n2 * 16 + ((lane >> 4) << 3) + (lane & 7);
                    const uint32_t c16b = ((lane >> 3) & 1) + 2 * ks;
                    LDSM4(b[2 * n2][0], b[2 * n2][1], b[2 * n2 + 1][0], b[2 * n2 + 1][1],
                          bS + sw64(rowb, c16b));
                }
                uint32_t a[MT][4];
#pragma unroll
                for (int mt = 0; mt < MT; mt++) {
                    const uint32_t rowa = wm0 + mt * 16 + (lane & 15);
                    LDSM4(a[mt][0], a[mt][1], a[mt][2], a[mt][3],
                          aS + sw64(rowa, (lane >> 4) + 2 * ks));
                }
#pragma unroll
                for (int mt = 0; mt < MT; mt++)
#pragma unroll
                    for (int nt = 0; nt < NT; nt++) MMA_F16(acc[mt][nt], a[mt], b[nt]);
            }
        }
    };

    // prologue: NSTAGE-1 stages in flight
#pragma unroll
    for (int p = 0; p < NSTAGE - 1; p++) produce(p);

    for (int c = 0; c < NCH2; c++) {
        if constexpr (NSTAGE == 3) CP_WAIT1(); else CP_WAIT2();
        __syncthreads();
        if (c + NSTAGE - 1 < NCH2) produce(c + NSTAGE - 1); else CP_COMMIT();
        if (c && (c & 7) == 0) {
            // Horner: entering next-lower j — scale accumulators by z
#pragma unroll
            for (int mt = 0; mt < MT; mt++)
#pragma unroll
                for (int nt = 0; nt < NT; nt++) {
                    acc[mt][nt][0] *= zA[mt]; acc[mt][nt][1] *= zA[mt];
                    acc[mt][nt][2] *= zB[mt]; acc[mt][nt][3] *= zB[mt];
                }
        }
        mma_stage(c % NSTAGE);
    }

    // epilogue: apply per-row scale, write f32
#pragma unroll
    for (int mt = 0; mt < MT; mt++) {
        const int row0 = m0 + wm0 + mt * 16 + (lane >> 2);
#pragma unroll
        for (int nt = 0; nt < NT; nt++) {
            const int col = n0 + wn0 + nt * 8 + (lane & 3) * 2;
            *reinterpret_cast<float2*>(&outF[(size_t)row0 * Ntotal + col]) =
                make_float2(acc[mt][nt][0] * sA[mt], acc[mt][nt][1] * sA[mt]);
            *reinterpret_cast<float2*>(&outF[(size_t)(row0 + 8) * Ntotal + col]) =
                make_float2(acc[mt][nt][2] * sB[mt], acc[mt][nt][3] * sB[mt]);
        }
    }
}

// ---------------------------------------------------------------------------
// Launch (graph-capturable, allocation-free)
// Inputs: z [B,D] f32, G0 [P,R] f32, G_mid [6,R,P,R] f32, G_last [R,P,OUT] f32, t
// Output: [B, OUT] f32
// ---------------------------------------------------------------------------
extern "C" void kernel_launch(void* const* d_in, const int* in_sizes, int n_in,
                              void* d_out, int out_size) {
    (void)in_sizes; (void)n_in; (void)out_size;
    const float* z     = (const float*)d_in[0];
    const float* G0    = (const float*)d_in[1];
    const float* Gmid  = (const float*)d_in[2];
    const float* Glast = (const float*)d_in[3];
    float* out = (float*)d_out;

    float *p_tg0, *p_resf, *p_sa;
    __half *p_qa, *p_bm, *p_bl;
    cudaGetSymbolAddress((void**)&p_tg0,  g_tanh_g0);
    cudaGetSymbolAddress((void**)&p_resf, g_resf);
    cudaGetSymbolAddress((void**)&p_sa,   g_sa);
    cudaGetSymbolAddress((void**)&p_qa,   g_qa);
    cudaGetSymbolAddress((void**)&p_bm,   g_b_mid);
    cudaGetSymbolAddress((void**)&p_bl,   g_b_last);

    // mids: 3 stages x 2 subs x (128+128)*64 = 98304 B/CTA -> 2 CTAs/SM
    const int SMEM_MID  = 3 * 2 * (128 + 128) * 64;  // 98304
    const int SMEM_LAST = 4 * 2 * (64 + 64) * 64;    // 65536
    cudaFuncSetAttribute((const void*)tt_mma_kernel<128, 128, 64, 64, 128, 2, 3>,
                         cudaFuncAttributeMaxDynamicSharedMemorySize, SMEM_MID);
    cudaFuncSetAttribute((const void*)tt_mma_kernel<64, 64, 32, 32, 128, 2, 4>,
                         cudaFuncAttributeMaxDynamicSharedMemorySize, SMEM_LAST);

    // precompute (fast tanh everywhere — err ~1e-6 << fp16 quantization)
    tanh_small_kernel<<<(P_SZ * R_SZ + 255) / 256, 256>>>(G0, p_tg0, P_SZ * R_SZ);
    trans_f16_kernel<<<dim3(R_SZ / 32, R_SZ / 32, NMID * P_SZ), dim3(32, 8)>>>(
        Gmid, p_bm, R_SZ, (size_t)R_SZ * P_SZ * R_SZ, (size_t)R_SZ * KTOT);
    trans_f16_kernel<<<dim3(R_SZ / 32, OUT_SZ / 32, P_SZ), dim3(32, 8)>>>(
        Glast, p_bl, OUT_SZ, 0, 0);

    // first core with fused quantization (one launch)
    first_core_quant_kernel<<<B_SZ, R_SZ>>>(z, p_qa, p_sa);

    // six middle cores: GEMM (f32 out) + per-row quantize — proven R16 config
    for (int i = 0; i < NMID; i++) {
        tt_mma_kernel<128, 128, 64, 64, 128, 2, 3>
            <<<dim3(R_SZ / 128, B_SZ / 128), 128, SMEM_MID>>>(
            p_qa, p_bm + (size_t)i * R_SZ * KTOT, p_sa,
            z, i + 1, p_resf, R_SZ);
        quant_res_kernel<<<B_SZ, 128>>>(p_resf, p_qa, p_sa);
    }

    // last core -> d_out [B, OUT] f32 — 128 threads, warp tile 32x32
    tt_mma_kernel<64, 64, 32, 32, 128, 2, 4><<<dim3(1, B_SZ / 64), 128, SMEM_LAST>>>(
        p_qa, p_bl, p_sa, z, D_SZ - 1, out, OUT_SZ);
}